// round 7
// baseline (speedup 1.0000x reference)
#include <cuda_runtime.h>
#include <math.h>

#define HEADS 4
#define RES 28
#define PSZ 14
#define PP 196
#define NB 32
#define NT 784
#define NC 768
#define CH 192
#define NCT 24            // channel tiles of 32
#define EPSF 1e-5f

// f32x2 packed helpers (FFMA2 is PTX-only; ptxas never auto-fuses)
#define PACK2(d, lo, hi) \
    asm("mov.b64 %0, {%1, %2};" : "=l"(d) : "f"(lo), "f"(hi))
#define UNPACK2(lo, hi, s) \
    asm("mov.b64 {%0, %1}, %2;" : "=f"(lo), "=f"(hi) : "l"(s))
#define FMA2(d, a, b, c) \
    asm("fma.rn.f32x2 %0, %1, %2, %3;" : "=l"(d) : "l"(a), "l"(b), "l"(c))

// ---- persistent device scratch (no allocations allowed) ----
__device__ float g_xp[(size_t)NB * NCT * PP * 32];  // pooled xn, [b][ctile][patch][32]
__device__ float g_inv[NB * HEADS * NT];            // [b][h][t]
__device__ float g_mln[NB * NT];
__device__ float g_vln[NB * NT];

// ============================================================
// K1: per-token group stats + pooled xp.  block = (b, patch j)
// ============================================================
__global__ void __launch_bounds__(192) k1_stats(const float* __restrict__ x) {
    int blk = blockIdx.x;
    int b = blk / PP, j = blk % PP;
    int py = j / 14, px = j % 14;
    int tid = threadIdx.x;
    int head = tid / 48;
    int c0 = head * CH + (tid % 48) * 4;
    int baseT = (2 * py) * 28 + 2 * px;

    float4 xv[4];
    float s1[4], s2[4];
    #pragma unroll
    for (int tok = 0; tok < 4; tok++) {
        int t = baseT + (tok >> 1) * 28 + (tok & 1);
        float4 v = __ldg((const float4*)(x + ((size_t)(b * NT + t)) * NC + c0));
        xv[tok] = v;
        s1[tok] = v.x + v.y + v.z + v.w;
        s2[tok] = v.x * v.x + v.y * v.y + v.z * v.z + v.w * v.w;
    }
    #pragma unroll
    for (int off = 8; off > 0; off >>= 1) {
        #pragma unroll
        for (int tok = 0; tok < 4; tok++) {
            s1[tok] += __shfl_down_sync(0xffffffffu, s1[tok], off, 16);
            s2[tok] += __shfl_down_sync(0xffffffffu, s2[tok], off, 16);
        }
    }
    __shared__ float rs1[12][4], rs2[12][4];            // [segment][tok]
    __shared__ float sS1[4][4], sS2[4][4], sInv[4][4];  // [tok][head]
    int seg = tid >> 4;
    if ((tid & 15) == 0) {
        #pragma unroll
        for (int tok = 0; tok < 4; tok++) { rs1[seg][tok] = s1[tok]; rs2[seg][tok] = s2[tok]; }
    }
    __syncthreads();
    if (tid < 16) {
        int tok = tid & 3, h = tid >> 2;
        float S1 = rs1[3 * h][tok] + rs1[3 * h + 1][tok] + rs1[3 * h + 2][tok];
        float S2 = rs2[3 * h][tok] + rs2[3 * h + 1][tok] + rs2[3 * h + 2][tok];
        float inv = rsqrtf(S2 * (1.0f / CH) + EPSF);
        sS1[tok][h] = S1; sS2[tok][h] = S2; sInv[tok][h] = inv;
        int t = baseT + (tok >> 1) * 28 + (tok & 1);
        g_inv[(b * HEADS + h) * NT + t] = inv;
    }
    __syncthreads();
    if (tid < 4) {
        int tok = tid;
        float sx = 0.f, sx2 = 0.f;
        #pragma unroll
        for (int h = 0; h < 4; h++) {
            float inv = sInv[tok][h];
            sx  += sS1[tok][h] * inv;
            sx2 += sS2[tok][h] * inv * inv;
        }
        float mean = sx * (1.0f / NC);
        float var = (sx2 - sx * mean) * (1.0f / (NC - 1));
        int t = baseT + (tok >> 1) * 28 + (tok & 1);
        g_mln[b * NT + t] = mean;
        g_vln[b * NT + t] = var;
    }
    float i0 = sInv[0][head], i1 = sInv[1][head], i2 = sInv[2][head], i3 = sInv[3][head];
    float4 o;
    o.x = 0.25f * (xv[0].x * i0 + xv[1].x * i1 + xv[2].x * i2 + xv[3].x * i3);
    o.y = 0.25f * (xv[0].y * i0 + xv[1].y * i1 + xv[2].y * i2 + xv[3].y * i3);
    o.z = 0.25f * (xv[0].z * i0 + xv[1].z * i1 + xv[2].z * i2 + xv[3].z * i3);
    o.w = 0.25f * (xv[0].w * i0 + xv[1].w * i1 + xv[2].w * i2 + xv[3].w * i3);
    int ct = c0 >> 5, ln = c0 & 31;
    *(float4*)&g_xp[(((size_t)(b * NCT + ct)) * PP + j) * 32 + ln] = o;
}

// ============================================================
// K2: separable pos-mix (f32x2 packed) + fused output epilogue.
// block = (b, 32-channel tile). 224 threads = 7 warps; warp g owns rows g, g+7.
// sT12: interleaved (mean, sq) per channel; 53KB smem, 4 blocks/SM.
// ============================================================
#define K2T 224
#define SM_FLOATS (12544 + 392 + 392)   // sT12 + sA2 + sB2 (float2-duplicated factors)

__global__ void __launch_bounds__(K2T, 4) k2_main(
        const float* __restrict__ x, const float* __restrict__ weight,
        const float* __restrict__ bias, const float* __restrict__ mnw,
        const float* __restrict__ vnw, const float* __restrict__ pw,
        float* __restrict__ out) {
    extern __shared__ float sm[];
    float* sT12 = sm;              // 196 rows x 32 ch x (mean, sq) interleaved
    float* sA2  = sm + 12544;      // 196 float2 (p,p)  y-factor [iy*14+jy]
    float* sB2  = sm + 12936;      // 196 float2 (p,p)  x-factor [ix*14+jx]

    int b = blockIdx.x;
    int ctile = blockIdx.y;
    int c0 = ctile * 32;
    int h = ctile / 6;             // 6 tiles per head
    int tid = threadIdx.x;

    float mwh = 1.0f / (1.0f + expf(-mnw[h]));
    float vwh = 1.0f / (1.0f + expf(-vnw[h]));
    float omm = 1.0f - mwh, omv = 1.0f - vwh;

    // in-block separable softmax factors, duplicated (p,p) for f32x2 use
    if (tid < 14) {                       // Bn: x-axis factor, column jx
        int jx = tid;
        float w0 = pw[h * 3 + 0], w2 = pw[h * 3 + 2];
        float s[14]; float mx = -1e30f;
        #pragma unroll
        for (int ix = 0; ix < 14; ix++) {
            float dx = (float)(jx - ix);
            float v = w0 * dx + w2 * dx * dx;
            s[ix] = v; mx = fmaxf(mx, v);
        }
        float sum = 0.f;
        #pragma unroll
        for (int ix = 0; ix < 14; ix++) { s[ix] = expf(s[ix] - mx); sum += s[ix]; }
        float r = 1.0f / sum;
        #pragma unroll
        for (int ix = 0; ix < 14; ix++) {
            float p = s[ix] * r;
            sB2[(ix * 14 + jx) * 2 + 0] = p;
            sB2[(ix * 14 + jx) * 2 + 1] = p;
        }
    } else if (tid >= 32 && tid < 46) {   // An: y-axis factor, column jy
        int jy = tid - 32;
        float w1 = pw[h * 3 + 1], w2 = pw[h * 3 + 2];
        float s[14]; float mx = -1e30f;
        #pragma unroll
        for (int iy = 0; iy < 14; iy++) {
            float dy = (float)(jy - iy);
            float v = w1 * dy + w2 * dy * dy;
            s[iy] = v; mx = fmaxf(mx, v);
        }
        float sum = 0.f;
        #pragma unroll
        for (int iy = 0; iy < 14; iy++) { s[iy] = expf(s[iy] - mx); sum += s[iy]; }
        float r = 1.0f / sum;
        #pragma unroll
        for (int iy = 0; iy < 14; iy++) {
            float p = s[iy] * r;
            sA2[(iy * 14 + jy) * 2 + 0] = p;
            sA2[(iy * 14 + jy) * 2 + 1] = p;
        }
    }
    __syncthreads();

    int g = tid >> 5, cl = tid & 31;     // warp g in [0,7), rows g and g+7
    const float* xpg = &g_xp[(((size_t)(b * NCT + ctile)) * PP) * 32];

    // ---- stage 1: contract over ix, f32x2 (value, square) packed; jx halves of 7
    #pragma unroll 1
    for (int hf = 0; hf < 2; hf++) {
        int j0 = hf * 7;
        unsigned long long acc0[7], acc1[7];
        #pragma unroll
        for (int jx = 0; jx < 7; jx++) { acc0[jx] = 0ull; acc1[jx] = 0ull; }
        #pragma unroll
        for (int ix = 0; ix < 14; ix++) {
            float v0 = __ldg(xpg + (((g    ) * 14 + ix) << 5) + cl);
            float v1 = __ldg(xpg + (((g + 7) * 14 + ix) << 5) + cl);
            unsigned long long vq0, vq1;
            PACK2(vq0, v0, v0 * v0);
            PACK2(vq1, v1, v1 * v1);
            #pragma unroll
            for (int jx = 0; jx < 7; jx++) {
                unsigned long long pp =
                    *(const unsigned long long*)(sB2 + (ix * 14 + j0 + jx) * 2);
                FMA2(acc0[jx], vq0, pp, acc0[jx]);
                FMA2(acc1[jx], vq1, pp, acc1[jx]);
            }
        }
        #pragma unroll
        for (int jx = 0; jx < 7; jx++) {
            *(unsigned long long*)(sT12 + (((g    ) * 14 + j0 + jx) << 6) + (cl << 1)) = acc0[jx];
            *(unsigned long long*)(sT12 + (((g + 7) * 14 + j0 + jx) << 6) + (cl << 1)) = acc1[jx];
        }
    }
    __syncthreads();

    // ---- stage 2: contract over iy (f32x2), write scaled (mean_r, var_r) in place
    #pragma unroll 1
    for (int hf = 0; hf < 2; hf++) {
        int j0 = hf * 7;
        unsigned long long m0[7], m1[7];
        #pragma unroll
        for (int jx = 0; jx < 7; jx++) { m0[jx] = 0ull; m1[jx] = 0ull; }
        #pragma unroll
        for (int iy = 0; iy < 14; iy++) {
            unsigned long long pa0 = *(const unsigned long long*)(sA2 + (iy * 14 + g    ) * 2);
            unsigned long long pa1 = *(const unsigned long long*)(sA2 + (iy * 14 + g + 7) * 2);
            #pragma unroll
            for (int jx = 0; jx < 7; jx++) {
                unsigned long long t12 =
                    *(const unsigned long long*)(sT12 + ((iy * 14 + j0 + jx) << 6) + (cl << 1));
                FMA2(m0[jx], pa0, t12, m0[jx]);
                FMA2(m1[jx], pa1, t12, m1[jx]);
            }
        }
        __syncthreads();   // all reads of this col-block done before overwrite
        #pragma unroll
        for (int jx = 0; jx < 7; jx++) {
            float mm, m2;
            UNPACK2(mm, m2, m0[jx]);
            float2 r0 = make_float2(omm * mm, omv * (m2 - mm * mm));
            *(float2*)(sT12 + (((g    ) * 14 + j0 + jx) << 6) + (cl << 1)) = r0;
            UNPACK2(mm, m2, m1[jx]);
            float2 r1 = make_float2(omm * mm, omv * (m2 - mm * mm));
            *(float2*)(sT12 + (((g + 7) * 14 + j0 + jx) << 6) + (cl << 1)) = r1;
        }
    }
    __syncthreads();

    // ---- fused epilogue: stream x -> out (float4, 4-deep batched loads)
    int q = tid & 7;                     // float4 slot within 32-ch tile
    int tb = tid >> 3;                   // token slot 0..27
    float4 wv = ((const float4*)(weight + c0))[q];
    float4 bv = ((const float4*)(bias   + c0))[q];
    const float* mlg = g_mln + b * NT;
    const float* vlg = g_vln + b * NT;
    const float* ivg = g_inv + (b * HEADS + h) * NT;
    const float4* xr  = (const float4*)(x   + (size_t)b * NT * NC + c0);
    float4*       orr = (float4*)      (out + (size_t)b * NT * NC + c0);
    const int rs = NC / 4;               // row stride in float4

    #pragma unroll 1
    for (int it = 0; it < 7; ++it) {
        float4 xv[4];
        float ml[4], vl[4], iv[4];
        #pragma unroll
        for (int u = 0; u < 4; u++) {
            int t = tb + (it * 4 + u) * 28;
            xv[u] = __ldg(&xr[(size_t)t * rs + q]);
            ml[u] = __ldg(mlg + t);
            vl[u] = __ldg(vlg + t);
            iv[u] = __ldg(ivg + t);
        }
        #pragma unroll
        for (int u = 0; u < 4; u++) {
            int t = tb + (it * 4 + u) * 28;
            unsigned row = (unsigned)t / 28u;
            unsigned col = (unsigned)t - row * 28u;
            int j = (int)((row >> 1) * 14 + (col >> 1));
            float inv = iv[u];
            float mlv = mwh * ml[u], vlv = vwh * vl[u];
            const float4* rw = (const float4*)(sT12 + (j << 6));
            float4 f0 = rw[2 * q];       // (m0,v0,m1,v1) for channels 4q,4q+1
            float4 f1 = rw[2 * q + 1];   // channels 4q+2,4q+3
            float4 o;
            o.x = (xv[u].x * inv - (f0.x + mlv)) * rsqrtf(f0.y + vlv + EPSF) * wv.x + bv.x;
            o.y = (xv[u].y * inv - (f0.z + mlv)) * rsqrtf(f0.w + vlv + EPSF) * wv.y + bv.y;
            o.z = (xv[u].z * inv - (f1.x + mlv)) * rsqrtf(f1.y + vlv + EPSF) * wv.z + bv.z;
            o.w = (xv[u].w * inv - (f1.z + mlv)) * rsqrtf(f1.w + vlv + EPSF) * wv.w + bv.w;
            orr[(size_t)t * rs + q] = o;
        }
    }
}

// ============================================================
extern "C" void kernel_launch(void* const* d_in, const int* in_sizes, int n_in,
                              void* d_out, int out_size) {
    const float* x      = (const float*)d_in[0];
    const float* weight = (const float*)d_in[1];
    const float* bias   = (const float*)d_in[2];
    const float* mnw    = (const float*)d_in[3];
    const float* vnw    = (const float*)d_in[4];
    const float* pw     = (const float*)d_in[5];
    // d_in[6] = pos_b: cancels inside the softmax, unused.
    float* out = (float*)d_out;

    cudaFuncSetAttribute(k2_main, cudaFuncAttributeMaxDynamicSharedMemorySize,
                         SM_FLOATS * (int)sizeof(float));

    k1_stats<<<NB * PP, 192>>>(x);
    k2_main<<<dim3(NB, NCT), K2T, SM_FLOATS * sizeof(float)>>>(
        x, weight, bias, mnw, vnw, pw, out);
}

// round 8
// speedup vs baseline: 1.0516x; 1.0516x over previous
#include <cuda_runtime.h>
#include <math.h>

#define HEADS 4
#define RES 28
#define PSZ 14
#define PP 196
#define NB 32
#define NT 784
#define NC 768
#define CH 192
#define NCT 24            // channel tiles of 32
#define EPSF 1e-5f

// ---- persistent device scratch (no allocations allowed) ----
__device__ float g_xp[(size_t)NB * NCT * PP * 32];  // pooled xn, [b][ctile][patch][32]
__device__ float g_inv[NB * HEADS * NT];            // [b][h][t]
__device__ float g_mln[NB * NT];
__device__ float g_vln[NB * NT];

// ============================================================
// K1: per-token group stats + pooled xp.  block = (b, patch j)
// 192 threads; thread owns 4 consecutive channels (float4).
// ============================================================
__global__ void __launch_bounds__(192) k1_stats(const float* __restrict__ x) {
    int blk = blockIdx.x;
    int b = blk / PP, j = blk % PP;
    int py = j / 14, px = j % 14;
    int tid = threadIdx.x;
    int head = tid / 48;
    int c0 = head * CH + (tid % 48) * 4;
    int baseT = (2 * py) * 28 + 2 * px;

    float4 xv[4];
    float s1[4], s2[4];
    #pragma unroll
    for (int tok = 0; tok < 4; tok++) {
        int t = baseT + (tok >> 1) * 28 + (tok & 1);
        float4 v = __ldg((const float4*)(x + ((size_t)(b * NT + t)) * NC + c0));
        xv[tok] = v;
        s1[tok] = v.x + v.y + v.z + v.w;
        s2[tok] = v.x * v.x + v.y * v.y + v.z * v.z + v.w * v.w;
    }
    #pragma unroll
    for (int off = 8; off > 0; off >>= 1) {
        #pragma unroll
        for (int tok = 0; tok < 4; tok++) {
            s1[tok] += __shfl_down_sync(0xffffffffu, s1[tok], off, 16);
            s2[tok] += __shfl_down_sync(0xffffffffu, s2[tok], off, 16);
        }
    }
    __shared__ float rs1[12][4], rs2[12][4];            // [segment][tok]
    __shared__ float sS1[4][4], sS2[4][4], sInv[4][4];  // [tok][head]
    int seg = tid >> 4;
    if ((tid & 15) == 0) {
        #pragma unroll
        for (int tok = 0; tok < 4; tok++) { rs1[seg][tok] = s1[tok]; rs2[seg][tok] = s2[tok]; }
    }
    __syncthreads();
    if (tid < 16) {
        int tok = tid & 3, h = tid >> 2;
        float S1 = rs1[3 * h][tok] + rs1[3 * h + 1][tok] + rs1[3 * h + 2][tok];
        float S2 = rs2[3 * h][tok] + rs2[3 * h + 1][tok] + rs2[3 * h + 2][tok];
        float inv = rsqrtf(S2 * (1.0f / CH) + EPSF);
        sS1[tok][h] = S1; sS2[tok][h] = S2; sInv[tok][h] = inv;
        int t = baseT + (tok >> 1) * 28 + (tok & 1);
        g_inv[(b * HEADS + h) * NT + t] = inv;
    }
    __syncthreads();
    if (tid < 4) {
        int tok = tid;
        float sx = 0.f, sx2 = 0.f;
        #pragma unroll
        for (int h = 0; h < 4; h++) {
            float inv = sInv[tok][h];
            sx  += sS1[tok][h] * inv;
            sx2 += sS2[tok][h] * inv * inv;
        }
        float mean = sx * (1.0f / NC);
        float var = (sx2 - sx * mean) * (1.0f / (NC - 1));
        int t = baseT + (tok >> 1) * 28 + (tok & 1);
        g_mln[b * NT + t] = mean;
        g_vln[b * NT + t] = var;
    }
    float i0 = sInv[0][head], i1 = sInv[1][head], i2 = sInv[2][head], i3 = sInv[3][head];
    float4 o;
    o.x = 0.25f * (xv[0].x * i0 + xv[1].x * i1 + xv[2].x * i2 + xv[3].x * i3);
    o.y = 0.25f * (xv[0].y * i0 + xv[1].y * i1 + xv[2].y * i2 + xv[3].y * i3);
    o.z = 0.25f * (xv[0].z * i0 + xv[1].z * i1 + xv[2].z * i2 + xv[3].z * i3);
    o.w = 0.25f * (xv[0].w * i0 + xv[1].w * i1 + xv[2].w * i2 + xv[3].w * i3);
    int ct = c0 >> 5, ln = c0 & 31;
    *(float4*)&g_xp[(((size_t)(b * NCT + ct)) * PP + j) * 32 + ln] = o;
}

// ============================================================
// K2: separable pos-mix + fused output epilogue, with L2 prefetch
// of the x-tile issued BEFORE the mix so DRAM fill overlaps FMA.
// block = (b, 32-channel tile). 224 threads = 7 warps; warp g owns rows g, g+7.
// ============================================================
#define K2T 224
#define SM_FLOATS (12544 + 784 + 392)   // sT1,sT2 + sINV + sA,sB

__global__ void __launch_bounds__(K2T, 4) k2_main(
        const float* __restrict__ x, const float* __restrict__ weight,
        const float* __restrict__ bias, const float* __restrict__ mnw,
        const float* __restrict__ vnw, const float* __restrict__ pw,
        float* __restrict__ out) {
    extern __shared__ float sm[];
    float* sT1  = sm;              // 196x32 stage-1 mean     (later: scaled mean_r)
    float* sT2  = sm + 6272;       // 196x32 stage-1 sq-mean  (later: scaled var_r)
    float* sINV = sm + 12544;      // 784  inv for this head
    float* sA   = sm + 13328;      // 196  y-factor [iy*14+jy]
    float* sB   = sm + 13524;      // 196  x-factor [ix*14+jx]

    int b = blockIdx.x;
    int ctile = blockIdx.y;
    int c0 = ctile * 32;
    int h = ctile / 6;             // 6 tiles per head
    int tid = threadIdx.x;

    // ---- L2 prefetch of this block's entire x-tile (one 128B line per token).
    // Issued first so the DRAM fetch overlaps the mix phase below.
    {
        const float* xbase = x + (size_t)b * NT * NC + c0;
        #pragma unroll 1
        for (int t = tid; t < NT; t += K2T) {
            asm volatile("prefetch.global.L2 [%0];" :: "l"(xbase + (size_t)t * NC));
        }
    }

    float mwh = 1.0f / (1.0f + expf(-mnw[h]));
    float vwh = 1.0f / (1.0f + expf(-vnw[h]));
    float omm = 1.0f - mwh, omv = 1.0f - vwh;

    // in-block separable softmax factors (pos_b cancels in softmax)
    if (tid < 14) {                       // Bn: x-axis factor, column jx
        int jx = tid;
        float w0 = pw[h * 3 + 0], w2 = pw[h * 3 + 2];
        float s[14]; float mx = -1e30f;
        #pragma unroll
        for (int ix = 0; ix < 14; ix++) {
            float dx = (float)(jx - ix);
            float v = w0 * dx + w2 * dx * dx;
            s[ix] = v; mx = fmaxf(mx, v);
        }
        float sum = 0.f;
        #pragma unroll
        for (int ix = 0; ix < 14; ix++) { s[ix] = expf(s[ix] - mx); sum += s[ix]; }
        float r = 1.0f / sum;
        #pragma unroll
        for (int ix = 0; ix < 14; ix++) sB[ix * 14 + jx] = s[ix] * r;
    } else if (tid >= 32 && tid < 46) {   // An: y-axis factor, column jy
        int jy = tid - 32;
        float w1 = pw[h * 3 + 1], w2 = pw[h * 3 + 2];
        float s[14]; float mx = -1e30f;
        #pragma unroll
        for (int iy = 0; iy < 14; iy++) {
            float dy = (float)(jy - iy);
            float v = w1 * dy + w2 * dy * dy;
            s[iy] = v; mx = fmaxf(mx, v);
        }
        float sum = 0.f;
        #pragma unroll
        for (int iy = 0; iy < 14; iy++) { s[iy] = expf(s[iy] - mx); sum += s[iy]; }
        float r = 1.0f / sum;
        #pragma unroll
        for (int iy = 0; iy < 14; iy++) sA[iy * 14 + jy] = s[iy] * r;
    }

    // token-stat prologue (inv only; mean/var loaded in epilogue from L2)
    {
        const float4* ig = (const float4*)(g_inv + (b * HEADS + h) * NT);
        float4* dI = (float4*)sINV;
        for (int i = tid; i < NT / 4; i += K2T) dI[i] = ig[i];
    }
    __syncthreads();

    int g = tid >> 5, cl = tid & 31;     // warp g in [0,7), rows g and g+7
    const float* xpg = &g_xp[(((size_t)(b * NCT + ctile)) * PP) * 32];

    // ---- stage 1: contract over ix, split jx into halves of 7 (reg diet)
    #pragma unroll 1
    for (int hf = 0; hf < 2; hf++) {
        int j0 = hf * 7;
        float a1[2][7], a2[2][7];
        #pragma unroll
        for (int jx = 0; jx < 7; jx++) { a1[0][jx] = a1[1][jx] = a2[0][jx] = a2[1][jx] = 0.f; }
        #pragma unroll
        for (int ix = 0; ix < 14; ix++) {
            float v0 = __ldg(xpg + (((g    ) * 14 + ix) << 5) + cl);
            float v1 = __ldg(xpg + (((g + 7) * 14 + ix) << 5) + cl);
            float q0 = v0 * v0, q1 = v1 * v1;
            #pragma unroll
            for (int jx = 0; jx < 7; jx++) {
                float p = sB[ix * 14 + j0 + jx];
                a1[0][jx] = fmaf(v0, p, a1[0][jx]);
                a2[0][jx] = fmaf(q0, p, a2[0][jx]);
                a1[1][jx] = fmaf(v1, p, a1[1][jx]);
                a2[1][jx] = fmaf(q1, p, a2[1][jx]);
            }
        }
        #pragma unroll
        for (int jx = 0; jx < 7; jx++) {
            sT1[(((g    ) * 14 + j0 + jx) << 5) + cl] = a1[0][jx];
            sT2[(((g    ) * 14 + j0 + jx) << 5) + cl] = a2[0][jx];
            sT1[(((g + 7) * 14 + j0 + jx) << 5) + cl] = a1[1][jx];
            sT2[(((g + 7) * 14 + j0 + jx) << 5) + cl] = a2[1][jx];
        }
    }
    __syncthreads();

    // ---- stage 2: contract over iy, split jx halves (read/write col-blocks
    // are disjoint per half, so one barrier between compute and write suffices)
    #pragma unroll 1
    for (int hf = 0; hf < 2; hf++) {
        int j0 = hf * 7;
        float m[2][7], m2[2][7];
        #pragma unroll
        for (int jx = 0; jx < 7; jx++) { m[0][jx] = m[1][jx] = m2[0][jx] = m2[1][jx] = 0.f; }
        #pragma unroll
        for (int iy = 0; iy < 14; iy++) {
            float p0 = sA[iy * 14 + g];
            float p1 = sA[iy * 14 + g + 7];
            #pragma unroll
            for (int jx = 0; jx < 7; jx++) {
                float t1v = sT1[((iy * 14 + j0 + jx) << 5) + cl];
                float t2v = sT2[((iy * 14 + j0 + jx) << 5) + cl];
                m [0][jx] = fmaf(p0, t1v, m [0][jx]);
                m2[0][jx] = fmaf(p0, t2v, m2[0][jx]);
                m [1][jx] = fmaf(p1, t1v, m [1][jx]);
                m2[1][jx] = fmaf(p1, t2v, m2[1][jx]);
            }
        }
        __syncthreads();   // all reads of this col-block done before overwrite
        #pragma unroll
        for (int jx = 0; jx < 7; jx++) {
            float mm = m[0][jx];
            sT1[(((g    ) * 14 + j0 + jx) << 5) + cl] = omm * mm;
            sT2[(((g    ) * 14 + j0 + jx) << 5) + cl] = omv * (m2[0][jx] - mm * mm);
            mm = m[1][jx];
            sT1[(((g + 7) * 14 + j0 + jx) << 5) + cl] = omm * mm;
            sT2[(((g + 7) * 14 + j0 + jx) << 5) + cl] = omv * (m2[1][jx] - mm * mm);
        }
    }
    __syncthreads();

    // ---- fused epilogue: stream x -> out (float4, 4-deep batched loads)
    int q = tid & 7;                     // float4 slot within 32-ch tile
    int tb = tid >> 3;                   // token slot 0..27
    float4 wv = ((const float4*)(weight + c0))[q];
    float4 bv = ((const float4*)(bias   + c0))[q];
    const float* mlg = g_mln + b * NT;
    const float* vlg = g_vln + b * NT;
    const float4* xr  = (const float4*)(x   + (size_t)b * NT * NC + c0);
    float4*       orr = (float4*)      (out + (size_t)b * NT * NC + c0);
    const int rs = NC / 4;               // row stride in float4

    #pragma unroll 1
    for (int it = 0; it < 7; ++it) {
        float4 xv[4];
        float ml[4], vl[4];
        #pragma unroll
        for (int u = 0; u < 4; u++) {
            int t = tb + (it * 4 + u) * 28;
            xv[u] = __ldg(&xr[(size_t)t * rs + q]);
            ml[u] = __ldg(mlg + t);
            vl[u] = __ldg(vlg + t);
        }
        #pragma unroll
        for (int u = 0; u < 4; u++) {
            int t = tb + (it * 4 + u) * 28;
            unsigned row = (unsigned)t / 28u;
            unsigned col = (unsigned)t - row * 28u;
            int j = (int)((row >> 1) * 14 + (col >> 1));
            float inv = sINV[t];
            float mlv = mwh * ml[u], vlv = vwh * vl[u];
            float4 mr = ((const float4*)(sT1 + (j << 5)))[q];
            float4 vr = ((const float4*)(sT2 + (j << 5)))[q];
            float4 o;
            o.x = (xv[u].x * inv - (mr.x + mlv)) * rsqrtf(vr.x + vlv + EPSF) * wv.x + bv.x;
            o.y = (xv[u].y * inv - (mr.y + mlv)) * rsqrtf(vr.y + vlv + EPSF) * wv.y + bv.y;
            o.z = (xv[u].z * inv - (mr.z + mlv)) * rsqrtf(vr.z + vlv + EPSF) * wv.z + bv.z;
            o.w = (xv[u].w * inv - (mr.w + mlv)) * rsqrtf(vr.w + vlv + EPSF) * wv.w + bv.w;
            orr[(size_t)t * rs + q] = o;
        }
    }
}

// ============================================================
extern "C" void kernel_launch(void* const* d_in, const int* in_sizes, int n_in,
                              void* d_out, int out_size) {
    const float* x      = (const float*)d_in[0];
    const float* weight = (const float*)d_in[1];
    const float* bias   = (const float*)d_in[2];
    const float* mnw    = (const float*)d_in[3];
    const float* vnw    = (const float*)d_in[4];
    const float* pw     = (const float*)d_in[5];
    // d_in[6] = pos_b: cancels inside the softmax, unused.
    float* out = (float*)d_out;

    cudaFuncSetAttribute(k2_main, cudaFuncAttributeMaxDynamicSharedMemorySize,
                         SM_FLOATS * (int)sizeof(float));

    k1_stats<<<NB * PP, 192>>>(x);
    k2_main<<<dim3(NB, NCT), K2T, SM_FLOATS * sizeof(float)>>>(
        x, weight, bias, mnw, vnw, pw, out);
}

// round 9
// speedup vs baseline: 1.0600x; 1.0080x over previous
#include <cuda_runtime.h>
#include <math.h>

#define HEADS 4
#define RES 28
#define PSZ 14
#define PP 196
#define NB 32
#define NT 784
#define NC 768
#define CH 192
#define NCT 24            // channel tiles of 32
#define EPSF 1e-5f

// ---- persistent device scratch (no allocations allowed) ----
__device__ float g_xp[(size_t)NB * NCT * PP * 32];  // pooled xn, [b][ctile][patch][32]
__device__ float g_inv[NB * HEADS * NT];            // [b][h][t]
__device__ float g_mln[NB * NT];
__device__ float g_vln[NB * NT];

// ============================================================
// K1: per-token group stats + pooled xp.  block = (b, patch j)
// 192 threads; thread owns 4 consecutive channels (float4).
// ============================================================
__global__ void __launch_bounds__(192) k1_stats(const float* __restrict__ x) {
    int blk = blockIdx.x;
    int b = blk / PP, j = blk % PP;
    int py = j / 14, px = j % 14;
    int tid = threadIdx.x;
    int head = tid / 48;
    int c0 = head * CH + (tid % 48) * 4;
    int baseT = (2 * py) * 28 + 2 * px;

    float4 xv[4];
    float s1[4], s2[4];
    #pragma unroll
    for (int tok = 0; tok < 4; tok++) {
        int t = baseT + (tok >> 1) * 28 + (tok & 1);
        float4 v = __ldg((const float4*)(x + ((size_t)(b * NT + t)) * NC + c0));
        xv[tok] = v;
        s1[tok] = v.x + v.y + v.z + v.w;
        s2[tok] = v.x * v.x + v.y * v.y + v.z * v.z + v.w * v.w;
    }
    #pragma unroll
    for (int off = 8; off > 0; off >>= 1) {
        #pragma unroll
        for (int tok = 0; tok < 4; tok++) {
            s1[tok] += __shfl_down_sync(0xffffffffu, s1[tok], off, 16);
            s2[tok] += __shfl_down_sync(0xffffffffu, s2[tok], off, 16);
        }
    }
    __shared__ float rs1[12][4], rs2[12][4];            // [segment][tok]
    __shared__ float sS1[4][4], sS2[4][4], sInv[4][4];  // [tok][head]
    int seg = tid >> 4;
    if ((tid & 15) == 0) {
        #pragma unroll
        for (int tok = 0; tok < 4; tok++) { rs1[seg][tok] = s1[tok]; rs2[seg][tok] = s2[tok]; }
    }
    __syncthreads();
    if (tid < 16) {
        int tok = tid & 3, h = tid >> 2;
        float S1 = rs1[3 * h][tok] + rs1[3 * h + 1][tok] + rs1[3 * h + 2][tok];
        float S2 = rs2[3 * h][tok] + rs2[3 * h + 1][tok] + rs2[3 * h + 2][tok];
        float inv = rsqrtf(S2 * (1.0f / CH) + EPSF);
        sS1[tok][h] = S1; sS2[tok][h] = S2; sInv[tok][h] = inv;
        int t = baseT + (tok >> 1) * 28 + (tok & 1);
        g_inv[(b * HEADS + h) * NT + t] = inv;
    }
    __syncthreads();
    if (tid < 4) {
        int tok = tid;
        float sx = 0.f, sx2 = 0.f;
        #pragma unroll
        for (int h = 0; h < 4; h++) {
            float inv = sInv[tok][h];
            sx  += sS1[tok][h] * inv;
            sx2 += sS2[tok][h] * inv * inv;
        }
        float mean = sx * (1.0f / NC);
        float var = (sx2 - sx * mean) * (1.0f / (NC - 1));
        int t = baseT + (tok >> 1) * 28 + (tok & 1);
        g_mln[b * NT + t] = mean;
        g_vln[b * NT + t] = var;
    }
    float i0 = sInv[0][head], i1 = sInv[1][head], i2 = sInv[2][head], i3 = sInv[3][head];
    float4 o;
    o.x = 0.25f * (xv[0].x * i0 + xv[1].x * i1 + xv[2].x * i2 + xv[3].x * i3);
    o.y = 0.25f * (xv[0].y * i0 + xv[1].y * i1 + xv[2].y * i2 + xv[3].y * i3);
    o.z = 0.25f * (xv[0].z * i0 + xv[1].z * i1 + xv[2].z * i2 + xv[3].z * i3);
    o.w = 0.25f * (xv[0].w * i0 + xv[1].w * i1 + xv[2].w * i2 + xv[3].w * i3);
    int ct = c0 >> 5, ln = c0 & 31;
    *(float4*)&g_xp[(((size_t)(b * NCT + ct)) * PP + j) * 32 + ln] = o;
}

// ============================================================
// K2: separable pos-mix + fused output epilogue.
// block = (b, 32-channel tile). 224 threads = 7 warps; warp g owns rows g, g+7.
// stage-1 inputs register-staged at block top; evict-first cache policy
// on single-use streams (x, g_xp reads; out writes).
// ============================================================
#define K2T 224
#define SM_FLOATS (12544 + 392)   // sT1,sT2 + sA,sB

__global__ void __launch_bounds__(K2T, 4) k2_main(
        const float* __restrict__ x, const float* __restrict__ weight,
        const float* __restrict__ bias, const float* __restrict__ mnw,
        const float* __restrict__ vnw, const float* __restrict__ pw,
        float* __restrict__ out) {
    extern __shared__ float sm[];
    float* sT1  = sm;              // 196x32 stage-1 mean     (later: scaled mean_r)
    float* sT2  = sm + 6272;       // 196x32 stage-1 sq-mean  (later: scaled var_r)
    float* sA   = sm + 12544;      // 196  y-factor [iy*14+jy]
    float* sB   = sm + 12740;      // 196  x-factor [ix*14+jx]

    int b = blockIdx.x;
    int ctile = blockIdx.y;
    int c0 = ctile * 32;
    int h = ctile / 6;             // 6 tiles per head
    int tid = threadIdx.x;
    int g = tid >> 5, cl = tid & 31;     // warp g in [0,7), rows g and g+7

    // ---- register-stage ALL stage-1 inputs up front (latency hides behind
    // factor expf + first barrier). Single-use lines -> evict-first.
    const float* xpg = &g_xp[(((size_t)(b * NCT + ctile)) * PP) * 32];
    float v0[14], v1[14];
    #pragma unroll
    for (int ix = 0; ix < 14; ix++) {
        v0[ix] = __ldcs(xpg + (((g    ) * 14 + ix) << 5) + cl);
        v1[ix] = __ldcs(xpg + (((g + 7) * 14 + ix) << 5) + cl);
    }

    float mwh = 1.0f / (1.0f + expf(-mnw[h]));
    float vwh = 1.0f / (1.0f + expf(-vnw[h]));
    float omm = 1.0f - mwh, omv = 1.0f - vwh;

    // in-block separable softmax factors (pos_b cancels in softmax)
    if (tid < 14) {                       // Bn: x-axis factor, column jx
        int jx = tid;
        float w0 = pw[h * 3 + 0], w2 = pw[h * 3 + 2];
        float s[14]; float mx = -1e30f;
        #pragma unroll
        for (int ix = 0; ix < 14; ix++) {
            float dx = (float)(jx - ix);
            float v = w0 * dx + w2 * dx * dx;
            s[ix] = v; mx = fmaxf(mx, v);
        }
        float sum = 0.f;
        #pragma unroll
        for (int ix = 0; ix < 14; ix++) { s[ix] = expf(s[ix] - mx); sum += s[ix]; }
        float r = 1.0f / sum;
        #pragma unroll
        for (int ix = 0; ix < 14; ix++) sB[ix * 14 + jx] = s[ix] * r;
    } else if (tid >= 32 && tid < 46) {   // An: y-axis factor, column jy
        int jy = tid - 32;
        float w1 = pw[h * 3 + 1], w2 = pw[h * 3 + 2];
        float s[14]; float mx = -1e30f;
        #pragma unroll
        for (int iy = 0; iy < 14; iy++) {
            float dy = (float)(jy - iy);
            float v = w1 * dy + w2 * dy * dy;
            s[iy] = v; mx = fmaxf(mx, v);
        }
        float sum = 0.f;
        #pragma unroll
        for (int iy = 0; iy < 14; iy++) { s[iy] = expf(s[iy] - mx); sum += s[iy]; }
        float r = 1.0f / sum;
        #pragma unroll
        for (int iy = 0; iy < 14; iy++) sA[iy * 14 + jy] = s[iy] * r;
    }
    __syncthreads();

    // ---- stage 1: contract over ix from registers, jx halves of 7
    #pragma unroll 1
    for (int hf = 0; hf < 2; hf++) {
        int j0 = hf * 7;
        float a1[2][7], a2[2][7];
        #pragma unroll
        for (int jx = 0; jx < 7; jx++) { a1[0][jx] = a1[1][jx] = a2[0][jx] = a2[1][jx] = 0.f; }
        #pragma unroll
        for (int ix = 0; ix < 14; ix++) {
            float x0 = v0[ix], x1 = v1[ix];
            float q0 = x0 * x0, q1 = x1 * x1;
            #pragma unroll
            for (int jx = 0; jx < 7; jx++) {
                float p = sB[ix * 14 + j0 + jx];
                a1[0][jx] = fmaf(x0, p, a1[0][jx]);
                a2[0][jx] = fmaf(q0, p, a2[0][jx]);
                a1[1][jx] = fmaf(x1, p, a1[1][jx]);
                a2[1][jx] = fmaf(q1, p, a2[1][jx]);
            }
        }
        #pragma unroll
        for (int jx = 0; jx < 7; jx++) {
            sT1[(((g    ) * 14 + j0 + jx) << 5) + cl] = a1[0][jx];
            sT2[(((g    ) * 14 + j0 + jx) << 5) + cl] = a2[0][jx];
            sT1[(((g + 7) * 14 + j0 + jx) << 5) + cl] = a1[1][jx];
            sT2[(((g + 7) * 14 + j0 + jx) << 5) + cl] = a2[1][jx];
        }
    }
    __syncthreads();

    // ---- stage 2: contract over iy, jx halves; in-place write after barrier
    #pragma unroll 1
    for (int hf = 0; hf < 2; hf++) {
        int j0 = hf * 7;
        float m[2][7], m2[2][7];
        #pragma unroll
        for (int jx = 0; jx < 7; jx++) { m[0][jx] = m[1][jx] = m2[0][jx] = m2[1][jx] = 0.f; }
        #pragma unroll
        for (int iy = 0; iy < 14; iy++) {
            float p0 = sA[iy * 14 + g];
            float p1 = sA[iy * 14 + g + 7];
            #pragma unroll
            for (int jx = 0; jx < 7; jx++) {
                float t1v = sT1[((iy * 14 + j0 + jx) << 5) + cl];
                float t2v = sT2[((iy * 14 + j0 + jx) << 5) + cl];
                m [0][jx] = fmaf(p0, t1v, m [0][jx]);
                m2[0][jx] = fmaf(p0, t2v, m2[0][jx]);
                m [1][jx] = fmaf(p1, t1v, m [1][jx]);
                m2[1][jx] = fmaf(p1, t2v, m2[1][jx]);
            }
        }
        __syncthreads();   // all reads of this col-block done before overwrite
        #pragma unroll
        for (int jx = 0; jx < 7; jx++) {
            float mm = m[0][jx];
            sT1[(((g    ) * 14 + j0 + jx) << 5) + cl] = omm * mm;
            sT2[(((g    ) * 14 + j0 + jx) << 5) + cl] = omv * (m2[0][jx] - mm * mm);
            mm = m[1][jx];
            sT1[(((g + 7) * 14 + j0 + jx) << 5) + cl] = omm * mm;
            sT2[(((g + 7) * 14 + j0 + jx) << 5) + cl] = omv * (m2[1][jx] - mm * mm);
        }
    }
    __syncthreads();

    // ---- fused epilogue: stream x -> out.
    // token t = row*28 + tb with tb = tid>>3 constant per thread:
    // column is constant -> no div/mod; j = (row>>1)*14 + (tb>>1).
    int q = tid & 7;                     // float4 slot within 32-ch tile
    int tb = tid >> 3;                   // image column 0..27 (constant)
    int jcol = tb >> 1;                  // patch column (constant)
    float4 wv = ((const float4*)(weight + c0))[q];
    float4 bv = ((const float4*)(bias   + c0))[q];
    const float* mlg = g_mln + b * NT;
    const float* vlg = g_vln + b * NT;
    const float* ivg = g_inv + (b * HEADS + h) * NT;
    const float4* xr  = (const float4*)(x   + (size_t)b * NT * NC + c0);
    float4*       orr = (float4*)      (out + (size_t)b * NT * NC + c0);
    const int rs = NC / 4;               // row stride in float4

    #pragma unroll 1
    for (int it = 0; it < 7; ++it) {
        float4 xv[4];
        float ml[4], vl[4], iv[4];
        #pragma unroll
        for (int u = 0; u < 4; u++) {
            int t = (it * 4 + u) * 28 + tb;
            xv[u] = __ldcs(&xr[(size_t)t * rs + q]);
            ml[u] = __ldg(mlg + t);
            vl[u] = __ldg(vlg + t);
            iv[u] = __ldg(ivg + t);
        }
        #pragma unroll
        for (int u = 0; u < 4; u++) {
            int row = it * 4 + u;
            int t = row * 28 + tb;
            int j = (row >> 1) * 14 + jcol;
            float inv = iv[u];
            float mlv = mwh * ml[u], vlv = vwh * vl[u];
            float4 mr = ((const float4*)(sT1 + (j << 5)))[q];
            float4 vr = ((const float4*)(sT2 + (j << 5)))[q];
            float4 o;
            o.x = (xv[u].x * inv - (mr.x + mlv)) * rsqrtf(vr.x + vlv + EPSF) * wv.x + bv.x;
            o.y = (xv[u].y * inv - (mr.y + mlv)) * rsqrtf(vr.y + vlv + EPSF) * wv.y + bv.y;
            o.z = (xv[u].z * inv - (mr.z + mlv)) * rsqrtf(vr.z + vlv + EPSF) * wv.z + bv.z;
            o.w = (xv[u].w * inv - (mr.w + mlv)) * rsqrtf(vr.w + vlv + EPSF) * wv.w + bv.w;
            __stcs(&orr[(size_t)t * rs + q], o);
        }
    }
}

// ============================================================
extern "C" void kernel_launch(void* const* d_in, const int* in_sizes, int n_in,
                              void* d_out, int out_size) {
    const float* x      = (const float*)d_in[0];
    const float* weight = (const float*)d_in[1];
    const float* bias   = (const float*)d_in[2];
    const float* mnw    = (const float*)d_in[3];
    const float* vnw    = (const float*)d_in[4];
    const float* pw     = (const float*)d_in[5];
    // d_in[6] = pos_b: cancels inside the softmax, unused.
    float* out = (float*)d_out;

    cudaFuncSetAttribute(k2_main, cudaFuncAttributeMaxDynamicSharedMemorySize,
                         SM_FLOATS * (int)sizeof(float));

    k1_stats<<<NB * PP, 192>>>(x);
    k2_main<<<dim3(NB, NCT), K2T, SM_FLOATS * sizeof(float)>>>(
        x, weight, bias, mnw, vnw, pw, out);
}

// round 10
// speedup vs baseline: 1.0862x; 1.0247x over previous
#include <cuda_runtime.h>
#include <math.h>

#define HEADS 4
#define RES 28
#define PSZ 14
#define PP 196
#define NB 32
#define NT 784
#define NC 768
#define CH 192
#define NCT 24            // channel tiles of 32
#define EPSF 1e-5f

// ---- persistent device scratch (no allocations allowed) ----
__device__ float g_xp[(size_t)NB * NCT * PP * 32];  // pooled xn, [b][ctile][patch][32]
__device__ float g_inv[NB * HEADS * NT];            // [b][h][t]
__device__ float g_mln[NB * NT];
__device__ float g_vln[NB * NT];

// ============================================================
// K1: per-token group stats + pooled xp.  block = (b, patch j)
// 192 threads; thread owns 4 consecutive channels (float4).
// ============================================================
__global__ void __launch_bounds__(192) k1_stats(const float* __restrict__ x) {
    int blk = blockIdx.x;
    int b = blk / PP, j = blk % PP;
    int py = j / 14, px = j % 14;
    int tid = threadIdx.x;
    int head = tid / 48;
    int c0 = head * CH + (tid % 48) * 4;
    int baseT = (2 * py) * 28 + 2 * px;

    float4 xv[4];
    float s1[4], s2[4];
    #pragma unroll
    for (int tok = 0; tok < 4; tok++) {
        int t = baseT + (tok >> 1) * 28 + (tok & 1);
        float4 v = __ldg((const float4*)(x + ((size_t)(b * NT + t)) * NC + c0));
        xv[tok] = v;
        s1[tok] = v.x + v.y + v.z + v.w;
        s2[tok] = v.x * v.x + v.y * v.y + v.z * v.z + v.w * v.w;
    }
    #pragma unroll
    for (int off = 8; off > 0; off >>= 1) {
        #pragma unroll
        for (int tok = 0; tok < 4; tok++) {
            s1[tok] += __shfl_down_sync(0xffffffffu, s1[tok], off, 16);
            s2[tok] += __shfl_down_sync(0xffffffffu, s2[tok], off, 16);
        }
    }
    __shared__ float rs1[12][4], rs2[12][4];            // [segment][tok]
    __shared__ float sS1[4][4], sS2[4][4], sInv[4][4];  // [tok][head]
    int seg = tid >> 4;
    if ((tid & 15) == 0) {
        #pragma unroll
        for (int tok = 0; tok < 4; tok++) { rs1[seg][tok] = s1[tok]; rs2[seg][tok] = s2[tok]; }
    }
    __syncthreads();
    if (tid < 16) {
        int tok = tid & 3, h = tid >> 2;
        float S1 = rs1[3 * h][tok] + rs1[3 * h + 1][tok] + rs1[3 * h + 2][tok];
        float S2 = rs2[3 * h][tok] + rs2[3 * h + 1][tok] + rs2[3 * h + 2][tok];
        float inv = rsqrtf(S2 * (1.0f / CH) + EPSF);
        sS1[tok][h] = S1; sS2[tok][h] = S2; sInv[tok][h] = inv;
        int t = baseT + (tok >> 1) * 28 + (tok & 1);
        g_inv[(b * HEADS + h) * NT + t] = inv;
    }
    __syncthreads();
    if (tid < 4) {
        int tok = tid;
        float sx = 0.f, sx2 = 0.f;
        #pragma unroll
        for (int h = 0; h < 4; h++) {
            float inv = sInv[tok][h];
            sx  += sS1[tok][h] * inv;
            sx2 += sS2[tok][h] * inv * inv;
        }
        float mean = sx * (1.0f / NC);
        float var = (sx2 - sx * mean) * (1.0f / (NC - 1));
        int t = baseT + (tok >> 1) * 28 + (tok & 1);
        g_mln[b * NT + t] = mean;
        g_vln[b * NT + t] = var;
    }
    float i0 = sInv[0][head], i1 = sInv[1][head], i2 = sInv[2][head], i3 = sInv[3][head];
    float4 o;
    o.x = 0.25f * (xv[0].x * i0 + xv[1].x * i1 + xv[2].x * i2 + xv[3].x * i3);
    o.y = 0.25f * (xv[0].y * i0 + xv[1].y * i1 + xv[2].y * i2 + xv[3].y * i3);
    o.z = 0.25f * (xv[0].z * i0 + xv[1].z * i1 + xv[2].z * i2 + xv[3].z * i3);
    o.w = 0.25f * (xv[0].w * i0 + xv[1].w * i1 + xv[2].w * i2 + xv[3].w * i3);
    int ct = c0 >> 5, ln = c0 & 31;
    *(float4*)&g_xp[(((size_t)(b * NCT + ct)) * PP + j) * 32 + ln] = o;
}

// ============================================================
// K2: separable pos-mix + fused output epilogue.  (R6 config)
// block = (b, 32-channel tile). 224 threads = 7 warps; warp g owns rows g, g+7.
// smem ~55KB; launch_bounds(224,4) -> 28 warps/SM; epilogue 7-deep batch.
// ============================================================
#define K2T 224
#define SM_FLOATS (12544 + 784 + 392)   // sT1,sT2 + sINV + sA,sB

__global__ void __launch_bounds__(K2T, 4) k2_main(
        const float* __restrict__ x, const float* __restrict__ weight,
        const float* __restrict__ bias, const float* __restrict__ mnw,
        const float* __restrict__ vnw, const float* __restrict__ pw,
        float* __restrict__ out) {
    extern __shared__ float sm[];
    float* sT1  = sm;              // 196x32 stage-1 mean     (later: scaled mean_r)
    float* sT2  = sm + 6272;       // 196x32 stage-1 sq-mean  (later: scaled var_r)
    float* sINV = sm + 12544;      // 784  inv for this head
    float* sA   = sm + 13328;      // 196  y-factor [iy*14+jy]
    float* sB   = sm + 13524;      // 196  x-factor [ix*14+jx]

    int b = blockIdx.x;
    int ctile = blockIdx.y;
    int c0 = ctile * 32;
    int h = ctile / 6;             // 6 tiles per head
    int tid = threadIdx.x;

    float mwh = 1.0f / (1.0f + expf(-mnw[h]));
    float vwh = 1.0f / (1.0f + expf(-vnw[h]));
    float omm = 1.0f - mwh, omv = 1.0f - vwh;

    // in-block separable softmax factors (pos_b cancels in softmax)
    if (tid < 14) {                       // Bn: x-axis factor, column jx
        int jx = tid;
        float w0 = pw[h * 3 + 0], w2 = pw[h * 3 + 2];
        float s[14]; float mx = -1e30f;
        #pragma unroll
        for (int ix = 0; ix < 14; ix++) {
            float dx = (float)(jx - ix);
            float v = w0 * dx + w2 * dx * dx;
            s[ix] = v; mx = fmaxf(mx, v);
        }
        float sum = 0.f;
        #pragma unroll
        for (int ix = 0; ix < 14; ix++) { s[ix] = expf(s[ix] - mx); sum += s[ix]; }
        float r = 1.0f / sum;
        #pragma unroll
        for (int ix = 0; ix < 14; ix++) sB[ix * 14 + jx] = s[ix] * r;
    } else if (tid >= 32 && tid < 46) {   // An: y-axis factor, column jy
        int jy = tid - 32;
        float w1 = pw[h * 3 + 1], w2 = pw[h * 3 + 2];
        float s[14]; float mx = -1e30f;
        #pragma unroll
        for (int iy = 0; iy < 14; iy++) {
            float dy = (float)(jy - iy);
            float v = w1 * dy + w2 * dy * dy;
            s[iy] = v; mx = fmaxf(mx, v);
        }
        float sum = 0.f;
        #pragma unroll
        for (int iy = 0; iy < 14; iy++) { s[iy] = expf(s[iy] - mx); sum += s[iy]; }
        float r = 1.0f / sum;
        #pragma unroll
        for (int iy = 0; iy < 14; iy++) sA[iy * 14 + jy] = s[iy] * r;
    }

    // token-stat prologue (inv only; mean/var loaded in epilogue from L2)
    {
        const float4* ig = (const float4*)(g_inv + (b * HEADS + h) * NT);
        float4* dI = (float4*)sINV;
        for (int i = tid; i < NT / 4; i += K2T) dI[i] = ig[i];
    }
    __syncthreads();

    int g = tid >> 5, cl = tid & 31;     // warp g in [0,7), rows g and g+7
    const float* xpg = &g_xp[(((size_t)(b * NCT + ctile)) * PP) * 32];

    // ---- stage 1: contract over ix, split jx into halves of 7 (reg diet)
    #pragma unroll 1
    for (int hf = 0; hf < 2; hf++) {
        int j0 = hf * 7;
        float a1[2][7], a2[2][7];
        #pragma unroll
        for (int jx = 0; jx < 7; jx++) { a1[0][jx] = a1[1][jx] = a2[0][jx] = a2[1][jx] = 0.f; }
        #pragma unroll
        for (int ix = 0; ix < 14; ix++) {
            float v0 = __ldg(xpg + (((g    ) * 14 + ix) << 5) + cl);
            float v1 = __ldg(xpg + (((g + 7) * 14 + ix) << 5) + cl);
            float q0 = v0 * v0, q1 = v1 * v1;
            #pragma unroll
            for (int jx = 0; jx < 7; jx++) {
                float p = sB[ix * 14 + j0 + jx];
                a1[0][jx] = fmaf(v0, p, a1[0][jx]);
                a2[0][jx] = fmaf(q0, p, a2[0][jx]);
                a1[1][jx] = fmaf(v1, p, a1[1][jx]);
                a2[1][jx] = fmaf(q1, p, a2[1][jx]);
            }
        }
        #pragma unroll
        for (int jx = 0; jx < 7; jx++) {
            sT1[(((g    ) * 14 + j0 + jx) << 5) + cl] = a1[0][jx];
            sT2[(((g    ) * 14 + j0 + jx) << 5) + cl] = a2[0][jx];
            sT1[(((g + 7) * 14 + j0 + jx) << 5) + cl] = a1[1][jx];
            sT2[(((g + 7) * 14 + j0 + jx) << 5) + cl] = a2[1][jx];
        }
    }
    __syncthreads();

    // ---- stage 2: contract over iy, split jx halves (read/write col-blocks
    // are disjoint per half, so one barrier between compute and write suffices)
    #pragma unroll 1
    for (int hf = 0; hf < 2; hf++) {
        int j0 = hf * 7;
        float m[2][7], m2[2][7];
        #pragma unroll
        for (int jx = 0; jx < 7; jx++) { m[0][jx] = m[1][jx] = m2[0][jx] = m2[1][jx] = 0.f; }
        #pragma unroll
        for (int iy = 0; iy < 14; iy++) {
            float p0 = sA[iy * 14 + g];
            float p1 = sA[iy * 14 + g + 7];
            #pragma unroll
            for (int jx = 0; jx < 7; jx++) {
                float t1v = sT1[((iy * 14 + j0 + jx) << 5) + cl];
                float t2v = sT2[((iy * 14 + j0 + jx) << 5) + cl];
                m [0][jx] = fmaf(p0, t1v, m [0][jx]);
                m2[0][jx] = fmaf(p0, t2v, m2[0][jx]);
                m [1][jx] = fmaf(p1, t1v, m [1][jx]);
                m2[1][jx] = fmaf(p1, t2v, m2[1][jx]);
            }
        }
        __syncthreads();   // all reads of this col-block done before overwrite
        #pragma unroll
        for (int jx = 0; jx < 7; jx++) {
            float mm = m[0][jx];
            sT1[(((g    ) * 14 + j0 + jx) << 5) + cl] = omm * mm;
            sT2[(((g    ) * 14 + j0 + jx) << 5) + cl] = omv * (m2[0][jx] - mm * mm);
            mm = m[1][jx];
            sT1[(((g + 7) * 14 + j0 + jx) << 5) + cl] = omm * mm;
            sT2[(((g + 7) * 14 + j0 + jx) << 5) + cl] = omv * (m2[1][jx] - mm * mm);
        }
    }
    __syncthreads();

    // ---- fused epilogue: stream x -> out (float4, 7-deep batched loads)
    int q = tid & 7;                     // float4 slot within 32-ch tile
    int tb = tid >> 3;                   // token slot 0..27
    float4 wv = ((const float4*)(weight + c0))[q];
    float4 bv = ((const float4*)(bias   + c0))[q];
    const float* mlg = g_mln + b * NT;
    const float* vlg = g_vln + b * NT;
    const float4* xr  = (const float4*)(x   + (size_t)b * NT * NC + c0);
    float4*       orr = (float4*)      (out + (size_t)b * NT * NC + c0);
    const int rs = NC / 4;               // row stride in float4

    #pragma unroll 1
    for (int it = 0; it < 4; ++it) {
        float4 xv[7];
        float ml[7], vl[7];
        #pragma unroll
        for (int u = 0; u < 7; u++) {
            int t = tb + (it * 7 + u) * 28;
            xv[u] = __ldg(&xr[(size_t)t * rs + q]);
            ml[u] = __ldg(mlg + t);
            vl[u] = __ldg(vlg + t);
        }
        #pragma unroll
        for (int u = 0; u < 7; u++) {
            int t = tb + (it * 7 + u) * 28;
            unsigned row = (unsigned)t / 28u;
            unsigned col = (unsigned)t - row * 28u;
            int j = (int)((row >> 1) * 14 + (col >> 1));
            float inv = sINV[t];
            float mlv = mwh * ml[u], vlv = vwh * vl[u];
            float4 mr = ((const float4*)(sT1 + (j << 5)))[q];
            float4 vr = ((const float4*)(sT2 + (j << 5)))[q];
            float4 o;
            o.x = (xv[u].x * inv - (mr.x + mlv)) * rsqrtf(vr.x + vlv + EPSF) * wv.x + bv.x;
            o.y = (xv[u].y * inv - (mr.y + mlv)) * rsqrtf(vr.y + vlv + EPSF) * wv.y + bv.y;
            o.z = (xv[u].z * inv - (mr.z + mlv)) * rsqrtf(vr.z + vlv + EPSF) * wv.z + bv.z;
            o.w = (xv[u].w * inv - (mr.w + mlv)) * rsqrtf(vr.w + vlv + EPSF) * wv.w + bv.w;
            orr[(size_t)t * rs + q] = o;
        }
    }
}

// ============================================================
extern "C" void kernel_launch(void* const* d_in, const int* in_sizes, int n_in,
                              void* d_out, int out_size) {
    const float* x      = (const float*)d_in[0];
    const float* weight = (const float*)d_in[1];
    const float* bias   = (const float*)d_in[2];
    const float* mnw    = (const float*)d_in[3];
    const float* vnw    = (const float*)d_in[4];
    const float* pw     = (const float*)d_in[5];
    // d_in[6] = pos_b: cancels inside the softmax, unused.
    float* out = (float*)d_out;

    cudaFuncSetAttribute(k2_main, cudaFuncAttributeMaxDynamicSharedMemorySize,
                         SM_FLOATS * (int)sizeof(float));

    k1_stats<<<NB * PP, 192>>>(x);
    k2_main<<<dim3(NB, NCT), K2T, SM_FLOATS * sizeof(float)>>>(
        x, weight, bias, mnw, vnw, pw, out);
}